// round 2
// baseline (speedup 1.0000x reference)
#include <cuda_runtime.h>
#include <math.h>

// Problem constants
#define SQ   2048            // sequence length
#define DM   1024            // model dim
#define NH   16              // query heads
#define NKV  4               // kv heads
#define HDIM 64              // head dim
#define NE   16              // experts
#define FFI  4096            // expert inner dim I
#define NTOP 4               // top-k
#define QKVN 1536            // (H + 2*KV)*HD

// ---------------- scratch (static __device__, per allocation rules) ----------------
__device__ float g_xln1 [SQ * DM];
__device__ float g_qkv  [SQ * QKVN];
__device__ float g_probs[67108864];      // 16 * 2048 * 2048
__device__ float g_attn [SQ * DM];
__device__ float g_hidden[SQ * DM];
__device__ float g_xln2 [SQ * DM];
__device__ float g_topv [SQ * NTOP];
__device__ int   g_topi [SQ * NTOP];
__device__ int   g_pos  [SQ * NTOP];
__device__ int   g_elist[NE * SQ];
__device__ int   g_ecnt [NE];
__device__ float g_abuf [134217728];     // 16 * 2048 * 4096  (silu-gated activations)
__device__ float g_y2   [33554432];      // 16 * 2048 * 1024  (expert outputs)

// ---------------- helpers ----------------
__device__ __forceinline__ float block_reduce(float v, int op /*0=sum 1=max*/) {
    __shared__ float sh[32];
    int lane = threadIdx.x & 31, w = threadIdx.x >> 5;
    #pragma unroll
    for (int o = 16; o; o >>= 1) {
        float t = __shfl_down_sync(0xffffffffu, v, o);
        v = op ? fmaxf(v, t) : v + t;
    }
    if (lane == 0) sh[w] = v;
    __syncthreads();
    int nw = blockDim.x >> 5;
    float r;
    if (threadIdx.x < 32) {
        float x = (threadIdx.x < nw) ? sh[threadIdx.x] : (op ? -INFINITY : 0.f);
        #pragma unroll
        for (int o = 16; o; o >>= 1) {
            float t = __shfl_down_sync(0xffffffffu, x, o);
            x = op ? fmaxf(x, t) : x + t;
        }
        if (threadIdx.x == 0) sh[0] = x;
    }
    __syncthreads();
    r = sh[0];
    __syncthreads();
    return r;
}

// ---------------- LayerNorm ----------------
__global__ void ln_kernel(const float* __restrict__ x, const float* __restrict__ w,
                          const float* __restrict__ b, float* __restrict__ out) {
    int row = blockIdx.x;
    const float* xr = x + (long)row * DM;
    float s = 0.f;
    for (int i = threadIdx.x; i < DM; i += blockDim.x) s += xr[i];
    float mean = block_reduce(s, 0) * (1.f / DM);
    float v = 0.f;
    for (int i = threadIdx.x; i < DM; i += blockDim.x) {
        float d = xr[i] - mean; v += d * d;
    }
    float var = block_reduce(v, 0) * (1.f / DM);
    float rstd = rsqrtf(var + 1e-5f);
    for (int i = threadIdx.x; i < DM; i += blockDim.x)
        out[(long)row * DM + i] = (xr[i] - mean) * rstd * w[i] + b[i];
}

// ---------------- Generic NT GEMM: C = A(MxK) * B(NxK)^T ----------------
// EPI: 0=plain 1=clip(+-p0) 2=scale(*p0) 3=add residual R
// CSKIP: skip tiles fully above causal diagonal (n0 >= m0+128)
template<int EPI, bool CSKIP>
__global__ __launch_bounds__(256)
void gemm_nt(const float* __restrict__ A, int lda, long long strideA,
             const float* __restrict__ B, int ldb, long long strideB, int zdivB,
             float* __restrict__ C, int ldc, long long strideC,
             int M, int N, int K,
             const int* __restrict__ counts,
             const float* __restrict__ R,
             float p0)
{
    int z = blockIdx.z;
    if (counts) M = counts[z];
    int m0 = blockIdx.y * 128;
    int n0 = blockIdx.x * 128;
    if (m0 >= M) return;
    if (CSKIP && n0 >= m0 + 128) return;
    A += (long long)z * strideA;
    B += (long long)(z / zdivB) * strideB;
    C += (long long)z * strideC;

    __shared__ float sA[16][128];
    __shared__ float sB[16][128];
    int tid = threadIdx.x;
    int tx = tid & 15, ty = tid >> 4;
    float acc[8][8];
    #pragma unroll
    for (int i = 0; i < 8; i++)
        #pragma unroll
        for (int j = 0; j < 8; j++) acc[i][j] = 0.f;

    for (int kk = 0; kk < K; kk += 16) {
        #pragma unroll
        for (int u = 0; u < 2; u++) {
            int idx = tid + u * 256;
            int r = idx >> 2, c4 = (idx & 3) * 4;
            float4 v = make_float4(0.f, 0.f, 0.f, 0.f);
            int gm = m0 + r;
            if (gm < M) v = *(const float4*)(A + (long long)gm * lda + kk + c4);
            sA[c4 + 0][r] = v.x; sA[c4 + 1][r] = v.y;
            sA[c4 + 2][r] = v.z; sA[c4 + 3][r] = v.w;
        }
        #pragma unroll
        for (int u = 0; u < 2; u++) {
            int idx = tid + u * 256;
            int r = idx >> 2, c4 = (idx & 3) * 4;
            float4 v = *(const float4*)(B + (long long)(n0 + r) * ldb + kk + c4);
            sB[c4 + 0][r] = v.x; sB[c4 + 1][r] = v.y;
            sB[c4 + 2][r] = v.z; sB[c4 + 3][r] = v.w;
        }
        __syncthreads();
        #pragma unroll
        for (int k = 0; k < 16; k++) {
            float af[8], bf[8];
            *(float4*)(af)     = *(const float4*)&sA[k][ty * 8];
            *(float4*)(af + 4) = *(const float4*)&sA[k][ty * 8 + 4];
            *(float4*)(bf)     = *(const float4*)&sB[k][tx * 8];
            *(float4*)(bf + 4) = *(const float4*)&sB[k][tx * 8 + 4];
            #pragma unroll
            for (int i = 0; i < 8; i++)
                #pragma unroll
                for (int j = 0; j < 8; j++)
                    acc[i][j] = fmaf(af[i], bf[j], acc[i][j]);
        }
        __syncthreads();
    }

    #pragma unroll
    for (int i = 0; i < 8; i++) {
        int gm = m0 + ty * 8 + i;
        if (gm >= M) break;
        float* crow = C + (long long)gm * ldc + n0 + tx * 8;
        #pragma unroll
        for (int j = 0; j < 8; j++) {
            float vv = acc[i][j];
            if (EPI == 1) vv = fminf(fmaxf(vv, -p0), p0);
            if (EPI == 2) vv *= p0;
            if (EPI == 3) vv += R[(long long)gm * ldc + n0 + tx * 8 + j];
            crow[j] = vv;
        }
    }
}

// ---------------- RoPE (q heads 0..15, k heads 16..19) ----------------
__global__ void rope_kernel(float* __restrict__ qkv, const int* __restrict__ pos_ids) {
    int s = blockIdx.y;
    int h = blockIdx.x;          // 0..NH+NKV-1
    int i = threadIdx.x;         // 0..31 (half headdim)
    float* base = qkv + (long long)s * QKVN + ((h < NH) ? h * HDIM : NH * HDIM + (h - NH) * HDIM);
    double inv = pow(500000.0, -(double)i / 32.0);
    double ang = (double)pos_ids[s] * inv;
    double c, sn;
    sincos(ang, &sn, &c);
    float x1 = base[i], x2 = base[i + 32];
    base[i]      = (float)((double)x1 * c - (double)x2 * sn);
    base[i + 32] = (float)((double)x2 * c + (double)x1 * sn);
}

// ---------------- causal softmax (+ zero-pad to 128 boundary for PV) ----------------
__global__ void softmax_causal(float* __restrict__ probs) {
    int s = blockIdx.x;
    int h = blockIdx.y;
    float* row = probs + (long long)h * SQ * SQ + (long long)s * SQ;
    int n = s + 1;
    float m = -INFINITY;
    for (int i = threadIdx.x; i < n; i += blockDim.x) m = fmaxf(m, row[i]);
    m = block_reduce(m, 1);
    float l = 0.f;
    for (int i = threadIdx.x; i < n; i += blockDim.x) {
        float e = expf(row[i] - m);
        row[i] = e;
        l += e;
    }
    l = block_reduce(l, 0);
    float inv = 1.f / l;
    for (int i = threadIdx.x; i < n; i += blockDim.x) row[i] *= inv;
    int padend = ((s >> 7) + 1) << 7;     // next multiple of 128
    for (int i = n + threadIdx.x; i < padend; i += blockDim.x) row[i] = 0.f;
}

// ---------------- PV GEMM (NN): attn[s, h*64+d] = sum_t P[s,t] * V[t,d], K limited causally ----------------
__global__ __launch_bounds__(256)
void gemm_pv(const float* __restrict__ probs, const float* __restrict__ qkv,
             float* __restrict__ attn)
{
    int h = blockIdx.z;
    int m0 = blockIdx.y * 128;
    const float* A = probs + (long long)h * SQ * SQ;
    const float* B = qkv + (NH + NKV) * HDIM + (h >> 2) * HDIM;  // v head h/4, ldb=QKVN
    int klimit = m0 + 128;

    __shared__ float sA[16][128];
    __shared__ float sB[16][64];
    int tid = threadIdx.x;
    int tx = tid & 15, ty = tid >> 4;
    float acc[8][4];
    #pragma unroll
    for (int i = 0; i < 8; i++)
        #pragma unroll
        for (int j = 0; j < 4; j++) acc[i][j] = 0.f;

    for (int kk = 0; kk < klimit; kk += 16) {
        #pragma unroll
        for (int u = 0; u < 2; u++) {
            int idx = tid + u * 256;
            int r = idx >> 2, c4 = (idx & 3) * 4;
            float4 v = *(const float4*)(A + (long long)(m0 + r) * SQ + kk + c4);
            sA[c4 + 0][r] = v.x; sA[c4 + 1][r] = v.y;
            sA[c4 + 2][r] = v.z; sA[c4 + 3][r] = v.w;
        }
        {
            int k = tid >> 4, n4 = (tid & 15) * 4;
            float4 v = *(const float4*)(B + (long long)(kk + k) * QKVN + n4);
            *(float4*)&sB[k][n4] = v;
        }
        __syncthreads();
        #pragma unroll
        for (int k = 0; k < 16; k++) {
            float af[8], bf[4];
            *(float4*)(af)     = *(const float4*)&sA[k][ty * 8];
            *(float4*)(af + 4) = *(const float4*)&sA[k][ty * 8 + 4];
            *(float4*)(bf)     = *(const float4*)&sB[k][tx * 4];
            #pragma unroll
            for (int i = 0; i < 8; i++)
                #pragma unroll
                for (int j = 0; j < 4; j++)
                    acc[i][j] = fmaf(af[i], bf[j], acc[i][j]);
        }
        __syncthreads();
    }
    #pragma unroll
    for (int i = 0; i < 8; i++) {
        int gm = m0 + ty * 8 + i;
        float* crow = attn + (long long)gm * DM + h * HDIM + tx * 4;
        #pragma unroll
        for (int j = 0; j < 4; j++) crow[j] = acc[i][j];
    }
}

// ---------------- router: logits, softmax, top-4, renormalize ----------------
__global__ void router_kernel(const float* __restrict__ x, const float* __restrict__ rw) {
    int t = blockIdx.x;
    int w = threadIdx.x >> 5;
    int lane = threadIdx.x & 31;
    __shared__ float sl[NE];
    const float* xr = x + (long long)t * DM;
    const float* wr = rw + (long long)w * DM;
    float sum = 0.f;
    for (int i = lane; i < DM; i += 32) sum += xr[i] * wr[i];
    #pragma unroll
    for (int o = 16; o; o >>= 1) sum += __shfl_down_sync(0xffffffffu, sum, o);
    if (lane == 0) sl[w] = sum;
    __syncthreads();
    if (threadIdx.x == 0) {
        float lg[NE], p[NE];
        float m = -INFINITY;
        #pragma unroll
        for (int e = 0; e < NE; e++) { lg[e] = sl[e]; m = fmaxf(m, lg[e]); }
        float s = 0.f;
        #pragma unroll
        for (int e = 0; e < NE; e++) { p[e] = expf(lg[e] - m); s += p[e]; }
        float invs = 1.f / s;
        #pragma unroll
        for (int e = 0; e < NE; e++) p[e] *= invs;
        bool used[NE];
        #pragma unroll
        for (int e = 0; e < NE; e++) used[e] = false;
        float tv[NTOP]; int ti[NTOP]; float tsum = 0.f;
        #pragma unroll
        for (int k = 0; k < NTOP; k++) {
            float best = -1.f; int bi = 0;
            #pragma unroll
            for (int e = 0; e < NE; e++)
                if (!used[e] && p[e] > best) { best = p[e]; bi = e; }
            used[bi] = true; tv[k] = best; ti[k] = bi; tsum += best;
        }
        float invt = 1.f / tsum;
        #pragma unroll
        for (int k = 0; k < NTOP; k++) {
            g_topv[t * NTOP + k] = tv[k] * invt;
            g_topi[t * NTOP + k] = ti[k];
        }
    }
}

// ---------------- deterministic expert token lists ----------------
__global__ void build_lists_kernel() {
    __shared__ int st[SQ * NTOP];   // 32 KB
    for (int i = threadIdx.x; i < SQ * NTOP; i += blockDim.x) st[i] = g_topi[i];
    __syncthreads();
    if (threadIdx.x < NE) {
        int e = threadIdx.x;
        int cnt = 0;
        for (int q = 0; q < SQ * NTOP; q++) {
            if (st[q] == e) {
                g_elist[e * SQ + cnt] = q >> 2;
                g_pos[q] = cnt;
                cnt++;
            }
        }
        g_ecnt[e] = cnt;
    }
}

// ---------------- MoE GEMM1: gathered rows, dual-weight, fused SiLU-GLU ----------------
__global__ __launch_bounds__(256)
void moe_gemm1(const float* __restrict__ x, const float* __restrict__ ws)
{
    int e = blockIdx.z;
    int cnt = g_ecnt[e];
    int m0 = blockIdx.y * 128;
    if (m0 >= cnt) return;
    int j0 = blockIdx.x * 64;
    const float* W1 = ws + (long long)e * (2LL * FFI * DM) + (long long)j0 * DM;
    const float* W2 = W1 + (long long)FFI * DM;

    __shared__ float sA[16][128];
    __shared__ float sB1[16][64];
    __shared__ float sB2[16][64];
    __shared__ int srow[128];
    int tid = threadIdx.x;
    if (tid < 128) {
        int i = m0 + tid;
        srow[tid] = (i < cnt) ? g_elist[e * SQ + i] : -1;
    }
    __syncthreads();
    int tx = tid & 15, ty = tid >> 4;
    float a1[8][4], a2[8][4];
    #pragma unroll
    for (int i = 0; i < 8; i++)
        #pragma unroll
        for (int j = 0; j < 4; j++) { a1[i][j] = 0.f; a2[i][j] = 0.f; }

    for (int kk = 0; kk < DM; kk += 16) {
        #pragma unroll
        for (int u = 0; u < 2; u++) {
            int idx = tid + u * 256;
            int r = idx >> 2, c4 = (idx & 3) * 4;
            int tok = srow[r];
            float4 v = make_float4(0.f, 0.f, 0.f, 0.f);
            if (tok >= 0) v = *(const float4*)(x + (long long)tok * DM + kk + c4);
            sA[c4 + 0][r] = v.x; sA[c4 + 1][r] = v.y;
            sA[c4 + 2][r] = v.z; sA[c4 + 3][r] = v.w;
        }
        {
            int r = tid >> 2, c4 = (tid & 3) * 4;
            float4 v = *(const float4*)(W1 + (long long)r * DM + kk + c4);
            sB1[c4 + 0][r] = v.x; sB1[c4 + 1][r] = v.y;
            sB1[c4 + 2][r] = v.z; sB1[c4 + 3][r] = v.w;
            float4 w = *(const float4*)(W2 + (long long)r * DM + kk + c4);
            sB2[c4 + 0][r] = w.x; sB2[c4 + 1][r] = w.y;
            sB2[c4 + 2][r] = w.z; sB2[c4 + 3][r] = w.w;
        }
        __syncthreads();
        #pragma unroll
        for (int k = 0; k < 16; k++) {
            float af[8], b1[4], b2[4];
            *(float4*)(af)     = *(const float4*)&sA[k][ty * 8];
            *(float4*)(af + 4) = *(const float4*)&sA[k][ty * 8 + 4];
            *(float4*)(b1)     = *(const float4*)&sB1[k][tx * 4];
            *(float4*)(b2)     = *(const float4*)&sB2[k][tx * 4];
            #pragma unroll
            for (int i = 0; i < 8; i++)
                #pragma unroll
                for (int j = 0; j < 4; j++) {
                    a1[i][j] = fmaf(af[i], b1[j], a1[i][j]);
                    a2[i][j] = fmaf(af[i], b2[j], a2[i][j]);
                }
        }
        __syncthreads();
    }
    #pragma unroll
    for (int i = 0; i < 8; i++) {
        int gi = m0 + ty * 8 + i;
        if (gi >= cnt) break;
        #pragma unroll
        for (int j = 0; j < 4; j++) {
            float h1 = a1[i][j], h2 = a2[i][j];
            float sig = 1.f / (1.f + expf(-h1));
            g_abuf[((long long)e * SQ + gi) * FFI + j0 + tx * 4 + j] = h1 * sig * h2;
        }
    }
}

// ---------------- final combine: residual + sum_k gate_k * y2 ----------------
__global__ void combine_kernel(float* __restrict__ out) {
    int t = blockIdx.x;
    __shared__ float gv[NTOP];
    __shared__ long long base[NTOP];
    if (threadIdx.x < NTOP) {
        int k = threadIdx.x;
        gv[k] = g_topv[t * NTOP + k];
        int e = g_topi[t * NTOP + k];
        int r = g_pos[t * NTOP + k];
        base[k] = ((long long)e * SQ + r) * DM;
    }
    __syncthreads();
    for (int d = threadIdx.x; d < DM; d += blockDim.x) {
        float acc = g_hidden[(long long)t * DM + d];
        #pragma unroll
        for (int k = 0; k < NTOP; k++)
            acc += gv[k] * g_y2[base[k] + d];
        out[(long long)t * DM + d] = acc;
    }
}

// ---------------- launch ----------------
extern "C" void kernel_launch(void* const* d_in, const int* in_sizes, int n_in,
                              void* d_out, int out_size) {
    const float* hs   = (const float*)d_in[0];
    const int*   pos  = (const int*)  d_in[1];
    const float* ln1w = (const float*)d_in[2];
    const float* ln1b = (const float*)d_in[3];
    const float* ln2w = (const float*)d_in[4];
    const float* ln2b = (const float*)d_in[5];
    const float* wqkv = (const float*)d_in[6];
    const float* wout = (const float*)d_in[7];
    const float* rw   = (const float*)d_in[8];
    const float* ws   = (const float*)d_in[9];
    const float* w2s  = (const float*)d_in[10];
    float* out = (float*)d_out;

    void* p;
    cudaGetSymbolAddress(&p, g_xln1);   float* xln1  = (float*)p;
    cudaGetSymbolAddress(&p, g_qkv);    float* qkv   = (float*)p;
    cudaGetSymbolAddress(&p, g_probs);  float* probs = (float*)p;
    cudaGetSymbolAddress(&p, g_attn);   float* attn  = (float*)p;
    cudaGetSymbolAddress(&p, g_hidden); float* hid   = (float*)p;
    cudaGetSymbolAddress(&p, g_xln2);   float* xln2  = (float*)p;
    cudaGetSymbolAddress(&p, g_abuf);   float* abuf  = (float*)p;
    cudaGetSymbolAddress(&p, g_y2);     float* y2    = (float*)p;
    cudaGetSymbolAddress(&p, g_ecnt);   int*   ecnt  = (int*)p;

    // 1) LN1
    ln_kernel<<<SQ, 256>>>(hs, ln1w, ln1b, xln1);
    // 2) QKV projection + clip
    gemm_nt<1, false><<<dim3(QKVN / 128, SQ / 128, 1), 256>>>(
        xln1, DM, 0, wqkv, DM, 0, 1, qkv, QKVN, 0,
        SQ, QKVN, DM, nullptr, nullptr, 8.0f);
    // 3) RoPE on q and k
    rope_kernel<<<dim3(NH + NKV, SQ), 32>>>(qkv, pos);
    // 4) scores = q k^T * scale (per head, causal tile skip)
    gemm_nt<2, true><<<dim3(SQ / 128, SQ / 128, NH), 256>>>(
        qkv, QKVN, 64, qkv + NH * HDIM, QKVN, 64, 4,
        probs, SQ, (long long)SQ * SQ,
        SQ, SQ, HDIM, nullptr, nullptr, 0.125f);
    // 5) causal softmax + pad
    softmax_causal<<<dim3(SQ, NH), 256>>>(probs);
    // 6) attn = P V (causal K-limit)
    gemm_pv<<<dim3(1, SQ / 128, NH), 256>>>(probs, qkv, attn);
    // 7) out projection + residual
    gemm_nt<3, false><<<dim3(DM / 128, SQ / 128, 1), 256>>>(
        attn, DM, 0, wout, DM, 0, 1, hid, DM, 0,
        SQ, DM, DM, nullptr, hs, 0.f);
    // 8) LN2
    ln_kernel<<<SQ, 256>>>(hid, ln2w, ln2b, xln2);
    // 9) router + top-4
    router_kernel<<<SQ, 512>>>(xln2, rw);
    // 10) expert token lists (deterministic)
    build_lists_kernel<<<1, 256>>>();
    // 11) MoE GEMM1 (gathered, dual-weight, fused SiLU-GLU)
    moe_gemm1<<<dim3(FFI / 64, SQ / 128, NE), 256>>>(xln2, ws);
    // 12) MoE GEMM2: y2 = a @ w2s^T per expert (count-guarded)
    gemm_nt<0, false><<<dim3(DM / 128, SQ / 128, NE), 256>>>(
        abuf, FFI, (long long)SQ * FFI,
        w2s, FFI, (long long)DM * FFI, 1,
        y2, DM, (long long)SQ * DM,
        SQ, DM, FFI, ecnt, nullptr, 0.f);
    // 13) combine: residual + gated expert outputs -> d_out
    combine_kernel<<<SQ, 256>>>(out);
}

// round 5
// speedup vs baseline: 2.1852x; 2.1852x over previous
#include <cuda_runtime.h>
#include <math.h>
#include <stdint.h>

#define SQ   2048
#define DM   1024
#define NH   16
#define NKV  4
#define HDIM 64
#define NE   16
#define FFI  4096
#define NTOP 4
#define QKVN 1536

// ---------------- static scratch ----------------
__device__ float g_xln1 [SQ*DM];
__device__ float g_qkv  [SQ*QKVN];
__device__ float g_probs[67108864];          // 16*2048*2048
__device__ float g_attn [SQ*DM];
__device__ float g_hidden[SQ*DM];
__device__ float g_xln2 [SQ*DM];
__device__ float g_topv [SQ*NTOP];
__device__ int   g_topi [SQ*NTOP];
__device__ int   g_pos  [SQ*NTOP];
__device__ int   g_elist[NE*SQ];
__device__ int   g_ecnt [NE];
__device__ int   g_eoff [NE];
__device__ float g_h    [67108864];          // 8192 x 8192 compact (h1|h2)
__device__ float g_abuf [33554432];          // 8192 x 4096
__device__ float g_y2   [8388608];           // 8192 x 1024

// ---------------- helpers ----------------
__device__ __forceinline__ float tf32r(float x) {
    uint32_t u; asm("cvt.rna.tf32.f32 %0, %1;" : "=r"(u) : "f"(x));
    return __uint_as_float(u);
}
__device__ __forceinline__ float block_reduce(float v, int op) {
    __shared__ float sh[32];
    int lane = threadIdx.x & 31, w = threadIdx.x >> 5;
    #pragma unroll
    for (int o = 16; o; o >>= 1) {
        float t = __shfl_down_sync(0xffffffffu, v, o);
        v = op ? fmaxf(v, t) : v + t;
    }
    if (lane == 0) sh[w] = v;
    __syncthreads();
    int nw = blockDim.x >> 5;
    if (threadIdx.x < 32) {
        float x = (threadIdx.x < nw) ? sh[threadIdx.x] : (op ? -INFINITY : 0.f);
        #pragma unroll
        for (int o = 16; o; o >>= 1) {
            float t = __shfl_down_sync(0xffffffffu, x, o);
            x = op ? fmaxf(x, t) : x + t;
        }
        if (threadIdx.x == 0) sh[0] = x;
    }
    __syncthreads();
    float r = sh[0];
    __syncthreads();
    return r;
}

// ---------------- LayerNorm ----------------
__global__ void ln_kernel(const float* __restrict__ x, const float* __restrict__ w,
                          const float* __restrict__ b, float* __restrict__ out) {
    int row = blockIdx.x;
    const float* xr = x + (long long)row * DM;
    float s = 0.f;
    for (int i = threadIdx.x; i < DM; i += blockDim.x) s += xr[i];
    float mean = block_reduce(s, 0) * (1.f / DM);
    float v = 0.f;
    for (int i = threadIdx.x; i < DM; i += blockDim.x) { float d = xr[i] - mean; v += d * d; }
    float rstd = rsqrtf(block_reduce(v, 0) * (1.f / DM) + 1e-5f);
    for (int i = threadIdx.x; i < DM; i += blockDim.x)
        out[(long long)row * DM + i] = (xr[i] - mean) * rstd * w[i] + b[i];
}

// ---------------- TF32 tensor-core NT GEMM: C = A(MxK) @ B(NxK)^T ----------------
// EPI: 0 plain, 1 clip(+-p0), 2 scale(*p0), 3 +R
template<int EPI, bool CSKIP, bool GATHER, bool COMPACT>
__global__ __launch_bounds__(256)
void tc_gemm(const float* __restrict__ A, int lda, long long strA,
             const float* __restrict__ B, int ldb, long long strB, int zdivB,
             float* __restrict__ C, int ldc, long long strC,
             int M, int N, int K,
             const float* __restrict__ R, float p0)
{
    int z = blockIdx.z;
    int Mloc = M;
    const int* rowlist = 0;
    if (COMPACT) {
        Mloc = g_ecnt[z];
        long long off = g_eoff[z];
        C += off * ldc;
        if (GATHER) rowlist = g_elist + z * SQ; else A += off * lda;
    } else {
        A += (long long)z * strA;
        C += (long long)z * strC;
    }
    B += (long long)(z / zdivB) * strB;
    int m0 = blockIdx.y * 128;
    if (m0 >= Mloc) return;
    int n0 = blockIdx.x * 128;
    if (CSKIP && n0 >= m0 + 128) return;

    __shared__ float sA[128][36];
    __shared__ float sB[128][36];
    __shared__ int srow[128];
    int tid = threadIdx.x;
    if (GATHER) {
        if (tid < 128) srow[tid] = (m0 + tid < Mloc) ? rowlist[m0 + tid] : -1;
        __syncthreads();
    }
    int l = tid & 31, wid = tid >> 5;
    int wm = wid & 1, wn = wid >> 1;       // warp tile: 64(M) x 32(N)
    float acc[4][4][4];
    #pragma unroll
    for (int i = 0; i < 4; i++)
        #pragma unroll
        for (int j = 0; j < 4; j++)
            #pragma unroll
            for (int q = 0; q < 4; q++) acc[i][j][q] = 0.f;

    for (int kk = 0; kk < K; kk += 32) {
        #pragma unroll
        for (int u = 0; u < 4; u++) {
            int i = tid + u * 256;
            int r = i >> 3, c = (i & 7) * 4;
            int gr; bool ok;
            if (GATHER) { gr = srow[r]; ok = gr >= 0; }
            else        { gr = m0 + r;  ok = gr < Mloc; }
            float4 v = make_float4(0.f, 0.f, 0.f, 0.f);
            if (ok) v = *(const float4*)(A + (long long)gr * lda + kk + c);
            sA[r][c]   = tf32r(v.x); sA[r][c+1] = tf32r(v.y);
            sA[r][c+2] = tf32r(v.z); sA[r][c+3] = tf32r(v.w);
        }
        #pragma unroll
        for (int u = 0; u < 4; u++) {
            int i = tid + u * 256;
            int r = i >> 3, c = (i & 7) * 4;
            float4 v = *(const float4*)(B + (long long)(n0 + r) * ldb + kk + c);
            sB[r][c]   = tf32r(v.x); sB[r][c+1] = tf32r(v.y);
            sB[r][c+2] = tf32r(v.z); sB[r][c+3] = tf32r(v.w);
        }
        __syncthreads();
        #pragma unroll
        for (int ks = 0; ks < 4; ks++) {
            int kc = ks * 8 + (l & 3);
            unsigned a[4][4], b[4][2];
            #pragma unroll
            for (int mt = 0; mt < 4; mt++) {
                int ar = wm * 64 + mt * 16 + (l >> 2);
                a[mt][0] = __float_as_uint(sA[ar][kc]);
                a[mt][1] = __float_as_uint(sA[ar + 8][kc]);
                a[mt][2] = __float_as_uint(sA[ar][kc + 4]);
                a[mt][3] = __float_as_uint(sA[ar + 8][kc + 4]);
            }
            #pragma unroll
            for (int nt = 0; nt < 4; nt++) {
                int bn = wn * 32 + nt * 8 + (l >> 2);
                b[nt][0] = __float_as_uint(sB[bn][kc]);
                b[nt][1] = __float_as_uint(sB[bn][kc + 4]);
            }
            #pragma unroll
            for (int mt = 0; mt < 4; mt++)
                #pragma unroll
                for (int nt = 0; nt < 4; nt++)
                    asm volatile(
                        "mma.sync.aligned.m16n8k8.row.col.f32.tf32.tf32.f32 "
                        "{%0,%1,%2,%3}, {%4,%5,%6,%7}, {%8,%9}, {%0,%1,%2,%3};"
                        : "+f"(acc[mt][nt][0]), "+f"(acc[mt][nt][1]),
                          "+f"(acc[mt][nt][2]), "+f"(acc[mt][nt][3])
                        : "r"(a[mt][0]), "r"(a[mt][1]), "r"(a[mt][2]), "r"(a[mt][3]),
                          "r"(b[nt][0]), "r"(b[nt][1]));
        }
        __syncthreads();
    }

    #pragma unroll
    for (int mt = 0; mt < 4; mt++) {
        int r0 = m0 + wm * 64 + mt * 16 + (l >> 2);
        int r1 = r0 + 8;
        #pragma unroll
        for (int nt = 0; nt < 4; nt++) {
            int col = n0 + wn * 32 + nt * 8 + ((l & 3) << 1);
            #pragma unroll
            for (int h = 0; h < 2; h++) {
                int rr = h ? r1 : r0;
                if (rr >= Mloc) continue;
                float c0 = acc[mt][nt][h * 2], c1 = acc[mt][nt][h * 2 + 1];
                if (EPI == 1) {
                    c0 = fminf(fmaxf(c0, -p0), p0);
                    c1 = fminf(fmaxf(c1, -p0), p0);
                }
                if (EPI == 2) { c0 *= p0; c1 *= p0; }
                if (EPI == 3) {
                    c0 += R[(long long)rr * ldc + col];
                    c1 += R[(long long)rr * ldc + col + 1];
                }
                C[(long long)rr * ldc + col]     = c0;
                C[(long long)rr * ldc + col + 1] = c1;
            }
        }
    }
}

// ---------------- RoPE ----------------
__global__ void rope_kernel(float* __restrict__ qkv, const int* __restrict__ pos_ids) {
    int s = blockIdx.x;
    int h = threadIdx.x >> 5;
    int i = threadIdx.x & 31;
    if (h >= NH + NKV) return;
    float* base = qkv + (long long)s * QKVN + h * HDIM;
    double inv = pow(500000.0, -(double)i / 32.0);
    double ang = (double)pos_ids[s] * inv;
    double sn, cs; sincos(ang, &sn, &cs);
    float x1 = base[i], x2 = base[i + 32];
    base[i]      = (float)((double)x1 * cs - (double)x2 * sn);
    base[i + 32] = (float)((double)x2 * cs + (double)x1 * sn);
}

// ---------------- causal softmax + pad to 128 ----------------
__global__ void softmax_causal(float* __restrict__ probs) {
    int s = blockIdx.x, h = blockIdx.y;
    float* row = probs + (long long)h * SQ * SQ + (long long)s * SQ;
    int n = s + 1;
    float m = -INFINITY;
    for (int i = threadIdx.x; i < n; i += blockDim.x) m = fmaxf(m, row[i]);
    m = block_reduce(m, 1);
    float lsum = 0.f;
    for (int i = threadIdx.x; i < n; i += blockDim.x) {
        float e = expf(row[i] - m); row[i] = e; lsum += e;
    }
    lsum = block_reduce(lsum, 0);
    float inv = 1.f / lsum;
    for (int i = threadIdx.x; i < n; i += blockDim.x) row[i] *= inv;
    int padend = ((s >> 7) + 1) << 7;
    for (int i = n + threadIdx.x; i < padend; i += blockDim.x) row[i] = 0.f;
}

// ---------------- PV GEMM (fp32) ----------------
__global__ __launch_bounds__(256)
void gemm_pv(const float* __restrict__ probs, const float* __restrict__ qkv,
             float* __restrict__ attn)
{
    int h = blockIdx.z;
    int m0 = blockIdx.y * 128;
    const float* A = probs + (long long)h * SQ * SQ;
    const float* B = qkv + (NH + NKV) * HDIM + (h >> 2) * HDIM;
    int klimit = m0 + 128;
    __shared__ float sA[16][128];
    __shared__ float sB[16][64];
    int tid = threadIdx.x, tx = tid & 15, ty = tid >> 4;
    float acc[8][4];
    #pragma unroll
    for (int i = 0; i < 8; i++)
        #pragma unroll
        for (int j = 0; j < 4; j++) acc[i][j] = 0.f;
    for (int kk = 0; kk < klimit; kk += 16) {
        #pragma unroll
        for (int u = 0; u < 2; u++) {
            int idx = tid + u * 256;
            int r = idx >> 2, c4 = (idx & 3) * 4;
            float4 v = *(const float4*)(A + (long long)(m0 + r) * SQ + kk + c4);
            sA[c4][r] = v.x; sA[c4+1][r] = v.y; sA[c4+2][r] = v.z; sA[c4+3][r] = v.w;
        }
        {
            int k = tid >> 4, n4 = (tid & 15) * 4;
            *(float4*)&sB[k][n4] = *(const float4*)(B + (long long)(kk + k) * QKVN + n4);
        }
        __syncthreads();
        #pragma unroll
        for (int k = 0; k < 16; k++) {
            float af[8], bf[4];
            *(float4*)(af)     = *(const float4*)&sA[k][ty * 8];
            *(float4*)(af + 4) = *(const float4*)&sA[k][ty * 8 + 4];
            *(float4*)(bf)     = *(const float4*)&sB[k][tx * 4];
            #pragma unroll
            for (int i = 0; i < 8; i++)
                #pragma unroll
                for (int j = 0; j < 4; j++) acc[i][j] = fmaf(af[i], bf[j], acc[i][j]);
        }
        __syncthreads();
    }
    #pragma unroll
    for (int i = 0; i < 8; i++) {
        int gm = m0 + ty * 8 + i;
        float* crow = attn + (long long)gm * DM + h * HDIM + tx * 4;
        #pragma unroll
        for (int j = 0; j < 4; j++) crow[j] = acc[i][j];
    }
}

// ---------------- router ----------------
__global__ void router_kernel(const float* __restrict__ x, const float* __restrict__ rw) {
    int t = blockIdx.x;
    int w = threadIdx.x >> 5, lane = threadIdx.x & 31;
    __shared__ float sl[NE];
    const float* xr = x + (long long)t * DM;
    const float* wr = rw + (long long)w * DM;
    float sum = 0.f;
    for (int i = lane; i < DM; i += 32) sum += xr[i] * wr[i];
    #pragma unroll
    for (int o = 16; o; o >>= 1) sum += __shfl_down_sync(0xffffffffu, sum, o);
    if (lane == 0) sl[w] = sum;
    __syncthreads();
    if (threadIdx.x == 0) {
        float p[NE], m = -INFINITY;
        #pragma unroll
        for (int e = 0; e < NE; e++) m = fmaxf(m, sl[e]);
        float s = 0.f;
        #pragma unroll
        for (int e = 0; e < NE; e++) { p[e] = expf(sl[e] - m); s += p[e]; }
        float invs = 1.f / s;
        #pragma unroll
        for (int e = 0; e < NE; e++) p[e] *= invs;
        bool used[NE];
        #pragma unroll
        for (int e = 0; e < NE; e++) used[e] = false;
        float tv[NTOP]; int ti[NTOP]; float tsum = 0.f;
        #pragma unroll
        for (int k = 0; k < NTOP; k++) {
            float best = -1.f; int bi = 0;
            #pragma unroll
            for (int e = 0; e < NE; e++)
                if (!used[e] && p[e] > best) { best = p[e]; bi = e; }
            used[bi] = true; tv[k] = best; ti[k] = bi; tsum += best;
        }
        float invt = 1.f / tsum;
        #pragma unroll
        for (int k = 0; k < NTOP; k++) {
            g_topv[t * NTOP + k] = tv[k] * invt;
            g_topi[t * NTOP + k] = ti[k];
        }
    }
}

// ---------------- expert lists + prefix offsets ----------------
__global__ void build_lists_kernel() {
    __shared__ int st[SQ * NTOP];
    for (int i = threadIdx.x; i < SQ * NTOP; i += blockDim.x) st[i] = g_topi[i];
    __syncthreads();
    if (threadIdx.x < NE) {
        int e = threadIdx.x, cnt = 0;
        for (int q = 0; q < SQ * NTOP; q++) {
            if (st[q] == e) {
                g_elist[e * SQ + cnt] = q >> 2;
                g_pos[q] = cnt;
                cnt++;
            }
        }
        g_ecnt[e] = cnt;
    }
    __syncthreads();
    if (threadIdx.x == 0) {
        int off = 0;
        for (int e = 0; e < NE; e++) { g_eoff[e] = off; off += g_ecnt[e]; }
    }
}

// ---------------- SiLU-GLU: abuf[r][j] = silu(h[r][j]) * h[r][j+4096] ----------------
__global__ void silu_kernel() {
    long long r = blockIdx.x;
    const float* hr = g_h + r * (2 * FFI);
    float* ar = g_abuf + r * FFI;
    for (int j = threadIdx.x * 4; j < FFI; j += blockDim.x * 4) {
        float4 h1 = *(const float4*)(hr + j);
        float4 h2 = *(const float4*)(hr + FFI + j);
        float4 o;
        o.x = h1.x / (1.f + expf(-h1.x)) * h2.x;
        o.y = h1.y / (1.f + expf(-h1.y)) * h2.y;
        o.z = h1.z / (1.f + expf(-h1.z)) * h2.z;
        o.w = h1.w / (1.f + expf(-h1.w)) * h2.w;
        *(float4*)(ar + j) = o;
    }
}

// ---------------- combine ----------------
__global__ void combine_kernel(float* __restrict__ out) {
    int t = blockIdx.x;
    __shared__ float gv[NTOP];
    __shared__ long long base[NTOP];
    if (threadIdx.x < NTOP) {
        int k = threadIdx.x;
        gv[k] = g_topv[t * NTOP + k];
        int e = g_topi[t * NTOP + k];
        base[k] = ((long long)g_eoff[e] + g_pos[t * NTOP + k]) * DM;
    }
    __syncthreads();
    for (int d = threadIdx.x; d < DM; d += blockDim.x) {
        float acc = g_hidden[(long long)t * DM + d];
        #pragma unroll
        for (int k = 0; k < NTOP; k++) acc += gv[k] * g_y2[base[k] + d];
        out[(long long)t * DM + d] = acc;
    }
}

// ---------------- launch ----------------
extern "C" void kernel_launch(void* const* d_in, const int* in_sizes, int n_in,
                              void* d_out, int out_size) {
    const float* hs   = (const float*)d_in[0];
    const int*   pos  = (const int*)  d_in[1];
    const float* ln1w = (const float*)d_in[2];
    const float* ln1b = (const float*)d_in[3];
    const float* ln2w = (const float*)d_in[4];
    const float* ln2b = (const float*)d_in[5];
    const float* wqkv = (const float*)d_in[6];
    const float* wout = (const float*)d_in[7];
    const float* rw   = (const float*)d_in[8];
    const float* ws   = (const float*)d_in[9];
    const float* w2s  = (const float*)d_in[10];
    float* out = (float*)d_out;

    void* p;
    cudaGetSymbolAddress(&p, g_xln1);   float* xln1  = (float*)p;
    cudaGetSymbolAddress(&p, g_qkv);    float* qkv   = (float*)p;
    cudaGetSymbolAddress(&p, g_probs);  float* probs = (float*)p;
    cudaGetSymbolAddress(&p, g_attn);   float* attn  = (float*)p;
    cudaGetSymbolAddress(&p, g_hidden); float* hid   = (float*)p;
    cudaGetSymbolAddress(&p, g_xln2);   float* xln2  = (float*)p;
    cudaGetSymbolAddress(&p, g_h);      float* hbuf  = (float*)p;
    cudaGetSymbolAddress(&p, g_abuf);   float* abuf  = (float*)p;
    cudaGetSymbolAddress(&p, g_y2);     float* y2    = (float*)p;

    // 1) LN1
    ln_kernel<<<SQ, 256>>>(hs, ln1w, ln1b, xln1);
    // 2) QKV + clip (TF32 TC)
    tc_gemm<1, false, false, false><<<dim3(QKVN/128, SQ/128, 1), 256>>>(
        xln1, DM, 0, wqkv, DM, 0, 1, qkv, QKVN, 0,
        SQ, QKVN, DM, nullptr, 8.0f);
    // 3) RoPE
    rope_kernel<<<SQ, 640>>>(qkv, pos);
    // 4) scores = q k^T * 0.125 (TF32 TC, causal tile skip)
    tc_gemm<2, true, false, false><<<dim3(SQ/128, SQ/128, NH), 256>>>(
        qkv, QKVN, 64, qkv + NH*HDIM, QKVN, 64, 4,
        probs, SQ, (long long)SQ*SQ,
        SQ, SQ, HDIM, nullptr, 0.125f);
    // 5) softmax
    softmax_causal<<<dim3(SQ, NH), 256>>>(probs);
    // 6) PV
    gemm_pv<<<dim3(1, SQ/128, NH), 256>>>(probs, qkv, attn);
    // 7) out-proj + residual (TF32 TC)
    tc_gemm<3, false, false, false><<<dim3(DM/128, SQ/128, 1), 256>>>(
        attn, DM, 0, wout, DM, 0, 1, hid, DM, 0,
        SQ, DM, DM, hs, 0.f);
    // 8) LN2
    ln_kernel<<<SQ, 256>>>(hid, ln2w, ln2b, xln2);
    // 9) router
    router_kernel<<<SQ, 512>>>(xln2, rw);
    // 10) expert lists + offsets
    build_lists_kernel<<<1, 256>>>();
    // 11) MoE GEMM1: h = gather(x) @ ws[e]^T (N=8192), compact rows
    tc_gemm<0, false, true, true><<<dim3(2*FFI/128, 16, NE), 256>>>(
        xln2, DM, 0, ws, DM, 2LL*FFI*DM, 1, hbuf, 2*FFI, 0,
        SQ, 2*FFI, DM, nullptr, 0.f);
    // 12) SiLU-GLU
    silu_kernel<<<SQ*NTOP, 256>>>();
    // 13) MoE GEMM2: y2 = abuf @ w2s[e]^T, compact
    tc_gemm<0, false, false, true><<<dim3(DM/128, 16, NE), 256>>>(
        abuf, FFI, 0, w2s, FFI, (long long)DM*FFI, 1, y2, DM, 0,
        SQ, DM, FFI, nullptr, 0.f);
    // 14) combine
    combine_kernel<<<SQ, 256>>>(out);
}